// round 17
// baseline (speedup 1.0000x reference)
#include <cuda_runtime.h>

#define NN 20000
#define BB 64
#define EE 1280000
#define TNB 625    // NN / 32 (exact)

// FINAL KERNEL — converged architecture (R11/R16 operating point, 64.0 us):
//   K1 prep:     smem-tiled transpose x[B,N]->xT[N,B] + accT zeroing (~6.5us)
//   K2 scatter:  half-warp/edge, LDG.128 gather + red.global.add.v4.f32
//                — pinned at the LTS chip byte-cap (~52us, the roofline)
//   K3 epilogue: tile-transpose accT->out with fused relu(acc*sl+b) (~6us)
//   K2/K3 are PDL secondaries: input-only prefixes overlap the predecessor;
//   cudaGridDependencySynchronize gates producer-output access.

// Scratch (allocation-free per rules).
__device__ __align__(16) float g_xT[NN * BB];    // xT[n*64 + b]
__device__ __align__(16) float g_accT[NN * BB];  // accT[n*64 + b]

// K1: smem-tiled transpose + zero accT. 625 x 512, one float4/thread/phase.
__global__ void __launch_bounds__(512)
prep_kernel(const float* __restrict__ x) {
    __shared__ float t[32][65];
    int tid = threadIdx.x;
    int n0 = blockIdx.x * 32;
    const float4* x4 = (const float4*)x;
    {
        int b = tid >> 3, q = tid & 7;
        float4 v = x4[b * (NN / 4) + (n0 >> 2) + q];
        int nc = 4 * q;
        t[nc + 0][b] = v.x;  t[nc + 1][b] = v.y;
        t[nc + 2][b] = v.z;  t[nc + 3][b] = v.w;
    }
    __syncthreads();
    {
        float4* xT4  = (float4*)g_xT;
        float4* acc4 = (float4*)g_accT;
        int nc = tid >> 4, bq = tid & 15;
        int n = n0 + nc;
        float4 v;
        v.x = t[nc][4 * bq + 0];  v.y = t[nc][4 * bq + 1];
        v.z = t[nc][4 * bq + 2];  v.w = t[nc][4 * bq + 3];
        xT4[n * 16 + bq]  = v;
        acc4[n * 16 + bq] = make_float4(0.f, 0.f, 0.f, 0.f);
    }
}

// K2: edge scatter, half-warp per edge (5000 x 256, measured-best shape).
__global__ void scatter_kernel(const float* __restrict__ adj,
                               const float* __restrict__ w,
                               const int* __restrict__ src,
                               const int* __restrict__ dst) {
    int g = (blockIdx.x * blockDim.x + threadIdx.x) >> 5;  // warp id
    int lane = threadIdx.x & 31;
    int e = g * 32 + lane;   // grid covers EE exactly

    // ---- independent prefix: overlaps with prep under PDL ----
    int   s = src[e];
    int   d = dst[e];
    float v = adj[e] * w[e];

    cudaGridDependencySynchronize();   // xT written, accT zeroed, visible

    int half = lane >> 4;
    int ll   = lane & 15;
    const float4* xT4 = (const float4*)g_xT;

    #pragma unroll 1
    for (int j = 0; j < 16; j++) {
        int sel = 2 * j + half;
        int   sj = __shfl_sync(0xffffffffu, s, sel);
        int   dj = __shfl_sync(0xffffffffu, d, sel);
        float vj = __shfl_sync(0xffffffffu, v, sel);

        float4 xv = xT4[sj * 16 + ll];           // LDG.128, coalesced, L2-hit
        float4 r;
        r.x = vj * xv.x;  r.y = vj * xv.y;
        r.z = vj * xv.z;  r.w = vj * xv.w;

        float* accp = &g_accT[dj * 64 + 4 * ll]; // 16B-aligned
        asm volatile("red.global.add.v4.f32 [%0], {%1, %2, %3, %4};"
                     :: "l"(accp), "f"(r.x), "f"(r.y), "f"(r.z), "f"(r.w)
                     : "memory");
    }
}

// K3: epilogue (625 x 512): accT tile-transpose + relu(acc*sl + b).
__global__ void __launch_bounds__(512)
epilogue_kernel(const float* __restrict__ x,
                const float* __restrict__ self_w,
                const float* __restrict__ bias,
                float* __restrict__ out) {
    __shared__ float tile[32][65];
    __shared__ float s_sl[32];
    __shared__ float s_b[32];
    int tid = threadIdx.x;
    int n0 = blockIdx.x * 32;

    // ---- independent prefix: overlaps with scatter tail under PDL ----
    if (tid < 32) {
        int n = n0 + tid;
        s_sl[tid] = x[n] * self_w[n];   // x[0, n] — faithful reference quirk
        s_b[tid]  = bias[n];
    }

    cudaGridDependencySynchronize();    // all atomics landed

    {
        const float4* acc4 = (const float4*)g_accT;
        int nc = tid >> 4, bq = tid & 15;
        int n = n0 + nc;
        float4 v = acc4[n * 16 + bq];
        tile[nc][4 * bq + 0] = v.x;
        tile[nc][4 * bq + 1] = v.y;
        tile[nc][4 * bq + 2] = v.z;
        tile[nc][4 * bq + 3] = v.w;
    }
    __syncthreads();
    {
        float4* out4 = (float4*)out;
        int b = tid >> 3, q = tid & 7;
        int nc = 4 * q;
        float4 r;
        r.x = fmaxf(fmaf(tile[nc + 0][b], s_sl[nc + 0], s_b[nc + 0]), 0.f);
        r.y = fmaxf(fmaf(tile[nc + 1][b], s_sl[nc + 1], s_b[nc + 1]), 0.f);
        r.z = fmaxf(fmaf(tile[nc + 2][b], s_sl[nc + 2], s_b[nc + 2]), 0.f);
        r.w = fmaxf(fmaf(tile[nc + 3][b], s_sl[nc + 3], s_b[nc + 3]), 0.f);
        out4[b * (NN / 4) + (n0 >> 2) + q] = r;
    }
}

extern "C" void kernel_launch(void* const* d_in, const int* in_sizes, int n_in,
                              void* d_out, int out_size) {
    const float* x      = (const float*)d_in[0];
    const float* adj    = (const float*)d_in[1];
    const float* w      = (const float*)d_in[2];
    const float* self_w = (const float*)d_in[3];
    const float* bias   = (const float*)d_in[4];
    const int*   src    = (const int*)d_in[5];
    const int*   dst    = (const int*)d_in[6];
    float* out = (float*)d_out;

    prep_kernel<<<TNB, 512>>>(x);

    cudaLaunchAttribute attr;
    attr.id = cudaLaunchAttributeProgrammaticStreamSerialization;
    attr.val.programmaticStreamSerializationAllowed = 1;

    {
        cudaLaunchConfig_t cfg = {};
        cfg.gridDim  = dim3(EE / 256);
        cfg.blockDim = dim3(256);
        cfg.attrs    = &attr;
        cfg.numAttrs = 1;
        cudaLaunchKernelEx(&cfg, scatter_kernel, adj, w, src, dst);
    }
    {
        cudaLaunchConfig_t cfg = {};
        cfg.gridDim  = dim3(TNB);
        cfg.blockDim = dim3(512);
        cfg.attrs    = &attr;
        cfg.numAttrs = 1;
        cudaLaunchKernelEx(&cfg, epilogue_kernel, x, self_w, bias, out);
    }
}